// round 1
// baseline (speedup 1.0000x reference)
#include <cuda_runtime.h>

// Problem dims (fixed by the reference)
static constexpr int B = 4, S = 2048, D = 512, H = 8, HD = 64;
static constexpr int N = B * S;                                   // 8192
static constexpr long long OUT_ELEMS  = (long long)B * S * D;     // 4,194,304
static constexpr long long ATTN_ELEMS = (long long)B * H * S * S; // 134,217,728

// Scratch (allocation-free rule: __device__ globals)
__device__ float g_Q[N * D];
__device__ float g_K[N * D];
__device__ float g_V[N * D];
__device__ float g_AV[N * D];
__device__ float g_attn[ATTN_ELEMS];   // used only if harness doesn't want attention output

// ---------------------------------------------------------------------------
// C[N,512] = X[N,512] @ W^T + bias   (W row-major [512,512], C[i,j]=sum_k X[i,k]W[j,k]+b[j])
// Tile 128x128, K-step 8, 256 threads, 8x8 per thread.
// ---------------------------------------------------------------------------
__global__ void __launch_bounds__(256) proj_gemm_kernel(
    const float* __restrict__ X, const float* __restrict__ W,
    const float* __restrict__ bias, float* __restrict__ C)
{
    __shared__ float Xs[8][132];   // padded: store addr = kk*132+m -> conflict-free
    __shared__ float Ws[8][132];

    const int bm = blockIdx.y * 128;
    const int bn = blockIdx.x * 128;
    const int tid = threadIdx.x;
    const int tm = (tid >> 4) * 8;   // 0..120
    const int tn = (tid & 15) * 8;

    float acc[8][8];
#pragma unroll
    for (int i = 0; i < 8; i++)
#pragma unroll
        for (int j = 0; j < 8; j++) acc[i][j] = 0.f;

    for (int k0 = 0; k0 < 512; k0 += 8) {
#pragma unroll
        for (int l = 0; l < 4; l++) {
            int e = tid + l * 256;
            int m = e >> 3, kk = e & 7;
            Xs[kk][m] = X[(long long)(bm + m) * 512 + k0 + kk];
            Ws[kk][m] = W[(long long)(bn + m) * 512 + k0 + kk];
        }
        __syncthreads();
#pragma unroll
        for (int kk = 0; kk < 8; kk++) {
            float a[8], bb[8];
#pragma unroll
            for (int i = 0; i < 8; i++) a[i] = Xs[kk][tm + i];
#pragma unroll
            for (int j = 0; j < 8; j++) bb[j] = Ws[kk][tn + j];
#pragma unroll
            for (int i = 0; i < 8; i++)
#pragma unroll
                for (int j = 0; j < 8; j++) acc[i][j] = fmaf(a[i], bb[j], acc[i][j]);
        }
        __syncthreads();
    }
#pragma unroll
    for (int i = 0; i < 8; i++) {
        float* crow = C + (long long)(bm + tm + i) * 512 + bn;
#pragma unroll
        for (int j = 0; j < 8; j++) crow[tn + j] = acc[i][j] + bias[bn + tn + j];
    }
}

// ---------------------------------------------------------------------------
// energy[b,h,q,k] = (1/8) * sum_d Q[b,q,h*64+d] * K[b,k,h*64+d], masked -> attn (raw)
// grid: (S/64 k-tiles, S/64 q-tiles, B*H); 64x64 tile, K=64 fully resident
// ---------------------------------------------------------------------------
__global__ void __launch_bounds__(256) scores_kernel(
    const float* __restrict__ Q, const float* __restrict__ K,
    const int* __restrict__ mask, float* __restrict__ attn)
{
    __shared__ float Qs[64][65];   // [d][m]
    __shared__ float Ks[64][65];   // [d][n]

    const int bh = blockIdx.z;
    const int b = bh / H, h = bh % H;
    const int q0 = blockIdx.y * 64;
    const int k0 = blockIdx.x * 64;
    const int tid = threadIdx.x;
    const int tm = (tid >> 4) * 4;
    const int tn = (tid & 15) * 4;

#pragma unroll
    for (int l = 0; l < 16; l++) {
        int e = tid + l * 256;
        int m = e >> 6, d = e & 63;
        Qs[d][m] = Q[((long long)(b * S + q0 + m)) * D + h * 64 + d];
        Ks[d][m] = K[((long long)(b * S + k0 + m)) * D + h * 64 + d];
    }
    __syncthreads();

    float acc[4][4];
#pragma unroll
    for (int i = 0; i < 4; i++)
#pragma unroll
        for (int j = 0; j < 4; j++) acc[i][j] = 0.f;

#pragma unroll
    for (int d = 0; d < 64; d++) {
        float a[4], bb[4];
#pragma unroll
        for (int i = 0; i < 4; i++) a[i] = Qs[d][tm + i];
#pragma unroll
        for (int j = 0; j < 4; j++) bb[j] = Ks[d][tn + j];
#pragma unroll
        for (int i = 0; i < 4; i++)
#pragma unroll
            for (int j = 0; j < 4; j++) acc[i][j] = fmaf(a[i], bb[j], acc[i][j]);
    }

    const float scale = 0.125f;  // 1/sqrt(64)
#pragma unroll
    for (int i = 0; i < 4; i++) {
        int q = q0 + tm + i;
        const int* mrow = mask + (long long)b * S * S + (long long)q * S;
        float* arow = attn + ((long long)bh * S + q) * S;
#pragma unroll
        for (int j = 0; j < 4; j++) {
            int k = k0 + tn + j;
            float e = acc[i][j] * scale;
            if (mrow[k] == 0) e = -1e20f;
            arow[k] = e;
        }
    }
}

// ---------------------------------------------------------------------------
// in-place row softmax over attn rows of length S=2048; 1 block per row
// ---------------------------------------------------------------------------
__global__ void __launch_bounds__(256) softmax_kernel(float* __restrict__ attn)
{
    float* p = attn + (long long)blockIdx.x * S;
    const int t = threadIdx.x;
    __shared__ float red[256];

    float v[8];
    float mx = -3.4e38f;
#pragma unroll
    for (int i = 0; i < 8; i++) { v[i] = p[t + i * 256]; mx = fmaxf(mx, v[i]); }

    red[t] = mx; __syncthreads();
    for (int s2 = 128; s2 > 0; s2 >>= 1) {
        if (t < s2) red[t] = fmaxf(red[t], red[t + s2]);
        __syncthreads();
    }
    mx = red[0];
    __syncthreads();

    float sum = 0.f;
#pragma unroll
    for (int i = 0; i < 8; i++) { v[i] = expf(v[i] - mx); sum += v[i]; }

    red[t] = sum; __syncthreads();
    for (int s2 = 128; s2 > 0; s2 >>= 1) {
        if (t < s2) red[t] += red[t + s2];
        __syncthreads();
    }
    float inv = 1.0f / red[0];
#pragma unroll
    for (int i = 0; i < 8; i++) p[t + i * 256] = v[i] * inv;
}

// ---------------------------------------------------------------------------
// OAV[b,q,h*64+d] = sum_k attn[b,h,q,k] * V[b,k,h*64+d]
// grid: (S/64 q-tiles, B*H); tile 64(q) x 64(d), K-chunks of 16
// ---------------------------------------------------------------------------
__global__ void __launch_bounds__(256) pv_kernel(
    const float* __restrict__ attn, const float* __restrict__ V,
    float* __restrict__ OAV)
{
    __shared__ float As[16][65];  // [kk][m]
    __shared__ float Vs[16][64];  // [kk][d]

    const int bh = blockIdx.y;
    const int b = bh / H, h = bh % H;
    const int q0 = blockIdx.x * 64;
    const int tid = threadIdx.x;
    const int tm = (tid >> 4) * 4;
    const int tn = (tid & 15) * 4;

    const float* arow = attn + ((long long)bh * S + q0) * S;

    float acc[4][4];
#pragma unroll
    for (int i = 0; i < 4; i++)
#pragma unroll
        for (int j = 0; j < 4; j++) acc[i][j] = 0.f;

    for (int k0 = 0; k0 < S; k0 += 16) {
#pragma unroll
        for (int l = 0; l < 4; l++) {
            int e = tid + l * 256;
            int m = e >> 4, kk = e & 15;
            As[kk][m] = arow[(long long)m * S + k0 + kk];
        }
#pragma unroll
        for (int l = 0; l < 4; l++) {
            int e = tid + l * 256;
            int kk = e >> 6, d = e & 63;
            Vs[kk][d] = V[((long long)(b * S + k0 + kk)) * D + h * 64 + d];
        }
        __syncthreads();
#pragma unroll
        for (int kk = 0; kk < 16; kk++) {
            float a[4], bb[4];
#pragma unroll
            for (int i = 0; i < 4; i++) a[i] = As[kk][tm + i];
#pragma unroll
            for (int j = 0; j < 4; j++) bb[j] = Vs[kk][tn + j];
#pragma unroll
            for (int i = 0; i < 4; i++)
#pragma unroll
                for (int j = 0; j < 4; j++) acc[i][j] = fmaf(a[i], bb[j], acc[i][j]);
        }
        __syncthreads();
    }

#pragma unroll
    for (int i = 0; i < 4; i++) {
        int q = q0 + tm + i;
        float* orow = OAV + ((long long)(b * S + q)) * D + h * 64;
#pragma unroll
        for (int j = 0; j < 4; j++) orow[tn + j] = acc[i][j];
    }
}

// ---------------------------------------------------------------------------
extern "C" void kernel_launch(void* const* d_in, const int* in_sizes, int n_in,
                              void* d_out, int out_size)
{
    const float* query = (const float*)d_in[0];
    const float* key   = (const float*)d_in[1];
    const float* value = (const float*)d_in[2];
    const int*   mask  = (const int*)d_in[3];
    const float* Wq = (const float*)d_in[4];
    const float* bq = (const float*)d_in[5];
    const float* Wk = (const float*)d_in[6];
    const float* bk = (const float*)d_in[7];
    const float* Wv = (const float*)d_in[8];
    const float* bv = (const float*)d_in[9];
    const float* Wo = (const float*)d_in[10];
    const float* bo = (const float*)d_in[11];

    float* out = (float*)d_out;

    void *pQ, *pK, *pV, *pAV, *pAttnScratch;
    cudaGetSymbolAddress(&pQ, g_Q);
    cudaGetSymbolAddress(&pK, g_K);
    cudaGetSymbolAddress(&pV, g_V);
    cudaGetSymbolAddress(&pAV, g_AV);
    cudaGetSymbolAddress(&pAttnScratch, g_attn);

    // If the harness's output includes the attention tensor (tuple output
    // flattened as [out, attention]), write it in place; otherwise use scratch.
    float* attn = ((long long)out_size >= OUT_ELEMS + ATTN_ELEMS)
                      ? out + OUT_ELEMS
                      : (float*)pAttnScratch;

    dim3 pg(D / 128, N / 128);  // (4, 64)
    proj_gemm_kernel<<<pg, 256>>>(query, Wq, bq, (float*)pQ);
    proj_gemm_kernel<<<pg, 256>>>(key,   Wk, bk, (float*)pK);
    proj_gemm_kernel<<<pg, 256>>>(value, Wv, bv, (float*)pV);

    scores_kernel<<<dim3(S / 64, S / 64, B * H), 256>>>(
        (const float*)pQ, (const float*)pK, mask, attn);

    softmax_kernel<<<B * H * S, 256>>>(attn);

    pv_kernel<<<dim3(S / 64, B * H), 256>>>(attn, (const float*)pV, (float*)pAV);

    proj_gemm_kernel<<<pg, 256>>>((const float*)pAV, Wo, bo, out);
}

// round 2
// speedup vs baseline: 1.1750x; 1.1750x over previous
#include <cuda_runtime.h>

static constexpr int B = 4, S = 2048, D = 512, H = 8, HD = 64;
static constexpr int N = B * S;                                   // 8192
static constexpr long long OUT_ELEMS  = (long long)B * S * D;     // 4,194,304
static constexpr long long ATTN_ELEMS = (long long)B * H * S * S; // 134,217,728

__device__ float g_Q[N * D];
__device__ float g_K[N * D];
__device__ float g_V[N * D];
__device__ float g_AV[N * D];
__device__ float g_attn[ATTN_ELEMS];

// ---------------------------------------------------------------------------
// C[N,512] = X[N,512] @ W^T + bias. Tile 128x128, K-chunk 16, 256 thr, 8x8.
// ---------------------------------------------------------------------------
__global__ void __launch_bounds__(256) proj_gemm_kernel(
    const float* __restrict__ X, const float* __restrict__ W,
    const float* __restrict__ bias, float* __restrict__ C)
{
    __shared__ float Xs[16][132];
    __shared__ float Ws[16][132];

    const int bm = blockIdx.y * 128;
    const int bn = blockIdx.x * 128;
    const int tid = threadIdx.x;
    const int tm = (tid >> 4) * 8;
    const int tn = (tid & 15) * 8;

    float acc[8][8];
#pragma unroll
    for (int i = 0; i < 8; i++)
#pragma unroll
        for (int j = 0; j < 8; j++) acc[i][j] = 0.f;

    for (int k0 = 0; k0 < 512; k0 += 16) {
#pragma unroll
        for (int l = 0; l < 2; l++) {
            int idx = tid + l * 256;          // 512 slots: 128 rows x 4 k-groups
            int m = idx >> 2, kg = (idx & 3) * 4;
            float4 x4 = *(const float4*)&X[(long long)(bm + m) * 512 + k0 + kg];
            Xs[kg + 0][m] = x4.x; Xs[kg + 1][m] = x4.y;
            Xs[kg + 2][m] = x4.z; Xs[kg + 3][m] = x4.w;
            float4 w4 = *(const float4*)&W[(long long)(bn + m) * 512 + k0 + kg];
            Ws[kg + 0][m] = w4.x; Ws[kg + 1][m] = w4.y;
            Ws[kg + 2][m] = w4.z; Ws[kg + 3][m] = w4.w;
        }
        __syncthreads();
#pragma unroll
        for (int kk = 0; kk < 16; kk++) {
            float4 a0 = *(const float4*)&Xs[kk][tm];
            float4 a1 = *(const float4*)&Xs[kk][tm + 4];
            float4 b0 = *(const float4*)&Ws[kk][tn];
            float4 b1 = *(const float4*)&Ws[kk][tn + 4];
            float a[8] = {a0.x, a0.y, a0.z, a0.w, a1.x, a1.y, a1.z, a1.w};
            float bb[8] = {b0.x, b0.y, b0.z, b0.w, b1.x, b1.y, b1.z, b1.w};
#pragma unroll
            for (int i = 0; i < 8; i++)
#pragma unroll
                for (int j = 0; j < 8; j++) acc[i][j] = fmaf(a[i], bb[j], acc[i][j]);
        }
        __syncthreads();
    }
#pragma unroll
    for (int i = 0; i < 8; i++) {
        float* crow = C + (long long)(bm + tm + i) * 512 + bn + tn;
        float4 o0, o1;
        o0.x = acc[i][0] + bias[bn + tn + 0]; o0.y = acc[i][1] + bias[bn + tn + 1];
        o0.z = acc[i][2] + bias[bn + tn + 2]; o0.w = acc[i][3] + bias[bn + tn + 3];
        o1.x = acc[i][4] + bias[bn + tn + 4]; o1.y = acc[i][5] + bias[bn + tn + 5];
        o1.z = acc[i][6] + bias[bn + tn + 6]; o1.w = acc[i][7] + bias[bn + tn + 7];
        *(float4*)&crow[0] = o0;
        *(float4*)&crow[4] = o1;
    }
}

// ---------------------------------------------------------------------------
// energy tile 128(q) x 128(k), d-chunks of 16, 256 thr, 8x8 microtile.
// ---------------------------------------------------------------------------
__global__ void __launch_bounds__(256) scores_kernel(
    const float* __restrict__ Q, const float* __restrict__ K,
    const int* __restrict__ mask, float* __restrict__ attn)
{
    __shared__ float Qs[16][132];
    __shared__ float Ks[16][132];

    const int bh = blockIdx.z;
    const int b = bh >> 3, h = bh & 7;
    const int q0 = blockIdx.y * 128;
    const int k0 = blockIdx.x * 128;
    const int tid = threadIdx.x;
    const int tm = (tid >> 4) * 8;
    const int tn = (tid & 15) * 8;

    float acc[8][8];
#pragma unroll
    for (int i = 0; i < 8; i++)
#pragma unroll
        for (int j = 0; j < 8; j++) acc[i][j] = 0.f;

    for (int d0 = 0; d0 < 64; d0 += 16) {
#pragma unroll
        for (int l = 0; l < 2; l++) {
            int idx = tid + l * 256;
            int m = idx >> 2, dg = (idx & 3) * 4;
            float4 q4 = *(const float4*)&Q[((long long)(b * S + q0 + m)) * 512 + h * 64 + d0 + dg];
            Qs[dg + 0][m] = q4.x; Qs[dg + 1][m] = q4.y;
            Qs[dg + 2][m] = q4.z; Qs[dg + 3][m] = q4.w;
            float4 k4 = *(const float4*)&K[((long long)(b * S + k0 + m)) * 512 + h * 64 + d0 + dg];
            Ks[dg + 0][m] = k4.x; Ks[dg + 1][m] = k4.y;
            Ks[dg + 2][m] = k4.z; Ks[dg + 3][m] = k4.w;
        }
        __syncthreads();
#pragma unroll
        for (int kk = 0; kk < 16; kk++) {
            float4 a0 = *(const float4*)&Qs[kk][tm];
            float4 a1 = *(const float4*)&Qs[kk][tm + 4];
            float4 b0 = *(const float4*)&Ks[kk][tn];
            float4 b1 = *(const float4*)&Ks[kk][tn + 4];
            float a[8] = {a0.x, a0.y, a0.z, a0.w, a1.x, a1.y, a1.z, a1.w};
            float bb[8] = {b0.x, b0.y, b0.z, b0.w, b1.x, b1.y, b1.z, b1.w};
#pragma unroll
            for (int i = 0; i < 8; i++)
#pragma unroll
                for (int j = 0; j < 8; j++) acc[i][j] = fmaf(a[i], bb[j], acc[i][j]);
        }
        __syncthreads();
    }

    const float scale = 0.125f;
#pragma unroll
    for (int i = 0; i < 8; i++) {
        int q = q0 + tm + i;
        const int* mrow = mask + (long long)b * S * S + (long long)q * S + k0 + tn;
        float* arow = attn + ((long long)bh * S + q) * S + k0 + tn;
        int4 m0 = *(const int4*)&mrow[0];
        int4 m1 = *(const int4*)&mrow[4];
        float4 e0, e1;
        e0.x = (m0.x == 0) ? -1e20f : acc[i][0] * scale;
        e0.y = (m0.y == 0) ? -1e20f : acc[i][1] * scale;
        e0.z = (m0.z == 0) ? -1e20f : acc[i][2] * scale;
        e0.w = (m0.w == 0) ? -1e20f : acc[i][3] * scale;
        e1.x = (m1.x == 0) ? -1e20f : acc[i][4] * scale;
        e1.y = (m1.y == 0) ? -1e20f : acc[i][5] * scale;
        e1.z = (m1.z == 0) ? -1e20f : acc[i][6] * scale;
        e1.w = (m1.w == 0) ? -1e20f : acc[i][7] * scale;
        *(float4*)&arow[0] = e0;
        *(float4*)&arow[4] = e1;
    }
}

// ---------------------------------------------------------------------------
// in-place row softmax, rows of 2048; float4, 1 block (256 thr) per row
// ---------------------------------------------------------------------------
__global__ void __launch_bounds__(256) softmax_kernel(float* __restrict__ attn)
{
    float4* p = (float4*)(attn + (long long)blockIdx.x * S);
    const int t = threadIdx.x;
    __shared__ float red[256];

    float4 v[2];
    float mx = -3.4e38f;
#pragma unroll
    for (int i = 0; i < 2; i++) {
        v[i] = p[t + i * 256];
        mx = fmaxf(mx, fmaxf(fmaxf(v[i].x, v[i].y), fmaxf(v[i].z, v[i].w)));
    }
    red[t] = mx; __syncthreads();
    for (int s2 = 128; s2 > 0; s2 >>= 1) {
        if (t < s2) red[t] = fmaxf(red[t], red[t + s2]);
        __syncthreads();
    }
    mx = red[0];
    __syncthreads();

    float sum = 0.f;
#pragma unroll
    for (int i = 0; i < 2; i++) {
        v[i].x = __expf(v[i].x - mx); v[i].y = __expf(v[i].y - mx);
        v[i].z = __expf(v[i].z - mx); v[i].w = __expf(v[i].w - mx);
        sum += v[i].x + v[i].y + v[i].z + v[i].w;
    }
    red[t] = sum; __syncthreads();
    for (int s2 = 128; s2 > 0; s2 >>= 1) {
        if (t < s2) red[t] += red[t + s2];
        __syncthreads();
    }
    float inv = 1.0f / red[0];
#pragma unroll
    for (int i = 0; i < 2; i++) {
        v[i].x *= inv; v[i].y *= inv; v[i].z *= inv; v[i].w *= inv;
        p[t + i * 256] = v[i];
    }
}

// ---------------------------------------------------------------------------
// OAV tile 128(q) x 64(d), k-chunks of 16, 128 thr, 8x8 microtile
// ---------------------------------------------------------------------------
__global__ void __launch_bounds__(128) pv_kernel(
    const float* __restrict__ attn, const float* __restrict__ V,
    float* __restrict__ OAV)
{
    __shared__ float As[16][132];
    __shared__ float Vs[16][68];

    const int bh = blockIdx.y;
    const int b = bh >> 3, h = bh & 7;
    const int q0 = blockIdx.x * 128;
    const int tid = threadIdx.x;
    const int tm = (tid >> 3) * 8;   // 0..120 (16 groups)
    const int tn = (tid & 7) * 8;    // 0..56  (8 groups)

    const float* arow = attn + ((long long)bh * S + q0) * S;

    float acc[8][8];
#pragma unroll
    for (int i = 0; i < 8; i++)
#pragma unroll
        for (int j = 0; j < 8; j++) acc[i][j] = 0.f;

    for (int k0 = 0; k0 < S; k0 += 16) {
        // A: 128 rows x 16 k = 512 float4 slots / 128 thr = 4 each
#pragma unroll
        for (int l = 0; l < 4; l++) {
            int idx = tid + l * 128;
            int m = idx >> 2, kg = (idx & 3) * 4;
            float4 a4 = *(const float4*)&arow[(long long)m * S + k0 + kg];
            As[kg + 0][m] = a4.x; As[kg + 1][m] = a4.y;
            As[kg + 2][m] = a4.z; As[kg + 3][m] = a4.w;
        }
        // V: 16 k x 64 d = 256 float4 slots / 128 thr = 2 each
#pragma unroll
        for (int l = 0; l < 2; l++) {
            int idx = tid + l * 128;
            int kk = idx >> 4, dg = (idx & 15) * 4;
            float4 v4 = *(const float4*)&V[((long long)(b * S + k0 + kk)) * 512 + h * 64 + dg];
            *(float4*)&Vs[kk][dg] = v4;
        }
        __syncthreads();
#pragma unroll
        for (int kk = 0; kk < 16; kk++) {
            float4 a0 = *(const float4*)&As[kk][tm];
            float4 a1 = *(const float4*)&As[kk][tm + 4];
            float4 b0 = *(const float4*)&Vs[kk][tn];
            float4 b1 = *(const float4*)&Vs[kk][tn + 4];
            float a[8] = {a0.x, a0.y, a0.z, a0.w, a1.x, a1.y, a1.z, a1.w};
            float bb[8] = {b0.x, b0.y, b0.z, b0.w, b1.x, b1.y, b1.z, b1.w};
#pragma unroll
            for (int i = 0; i < 8; i++)
#pragma unroll
                for (int j = 0; j < 8; j++) acc[i][j] = fmaf(a[i], bb[j], acc[i][j]);
        }
        __syncthreads();
    }

#pragma unroll
    for (int i = 0; i < 8; i++) {
        float* orow = OAV + ((long long)(b * S + q0 + tm + i)) * 512 + h * 64 + tn;
        float4 o0 = {acc[i][0], acc[i][1], acc[i][2], acc[i][3]};
        float4 o1 = {acc[i][4], acc[i][5], acc[i][6], acc[i][7]};
        *(float4*)&orow[0] = o0;
        *(float4*)&orow[4] = o1;
    }
}

// ---------------------------------------------------------------------------
extern "C" void kernel_launch(void* const* d_in, const int* in_sizes, int n_in,
                              void* d_out, int out_size)
{
    const float* query = (const float*)d_in[0];
    const float* key   = (const float*)d_in[1];
    const float* value = (const float*)d_in[2];
    const int*   mask  = (const int*)d_in[3];
    const float* Wq = (const float*)d_in[4];
    const float* bq = (const float*)d_in[5];
    const float* Wk = (const float*)d_in[6];
    const float* bk = (const float*)d_in[7];
    const float* Wv = (const float*)d_in[8];
    const float* bv = (const float*)d_in[9];
    const float* Wo = (const float*)d_in[10];
    const float* bo = (const float*)d_in[11];

    float* out = (float*)d_out;

    void *pQ, *pK, *pV, *pAV, *pAttnScratch;
    cudaGetSymbolAddress(&pQ, g_Q);
    cudaGetSymbolAddress(&pK, g_K);
    cudaGetSymbolAddress(&pV, g_V);
    cudaGetSymbolAddress(&pAV, g_AV);
    cudaGetSymbolAddress(&pAttnScratch, g_attn);

    float* attn = ((long long)out_size >= OUT_ELEMS + ATTN_ELEMS)
                      ? out + OUT_ELEMS
                      : (float*)pAttnScratch;

    dim3 pg(D / 128, N / 128);  // (4, 64)
    proj_gemm_kernel<<<pg, 256>>>(query, Wq, bq, (float*)pQ);
    proj_gemm_kernel<<<pg, 256>>>(key,   Wk, bk, (float*)pK);
    proj_gemm_kernel<<<pg, 256>>>(value, Wv, bv, (float*)pV);

    scores_kernel<<<dim3(S / 128, S / 128, B * H), 256>>>(
        (const float*)pQ, (const float*)pK, mask, attn);

    softmax_kernel<<<B * H * S, 256>>>(attn);

    pv_kernel<<<dim3(S / 128, B * H), 128>>>(attn, (const float*)pV, (float*)pAV);

    proj_gemm_kernel<<<pg, 256>>>((const float*)pAV, Wo, bo, out);
}